// round 1
// baseline (speedup 1.0000x reference)
#include <cuda_runtime.h>
#include <math.h>

#define EMBED   1024
#define KDIM    64
#define HEADS   16
#define BATCH   4
#define SEQ     2048
#define TOKENS  (BATCH * SEQ)      /* 8192 */
#define QKVW    (3 * EMBED)        /* 3072 */

// Scratch (allocation-free rule: __device__ globals)
__device__ float g_qkv[(size_t)TOKENS * QKVW];    // [token][3072]: q | k | v, each [h*64+k]
__device__ float g_heads[(size_t)TOKENS * EMBED]; // [token][h*64+k]

// ---------------------------------------------------------------------------
// SGEMM body: 128x128 C tile, BK=8, 256 threads, 8x8 per-thread microtile.
// Athr: &A[(bm + tid/2)*lda + (tid&1)*4]        (A row-major, lda = K stride)
// Bthr: element (row = tid/32, this thread's col) ; advance by k0*ldb
// Cblk: &C[bm*ldc + bn]
// ---------------------------------------------------------------------------
__device__ __forceinline__ void sgemm_tile(
    const float* __restrict__ Athr,
    const float* __restrict__ Bthr, int ldb,
    float* __restrict__ Cblk, int ldc, int Kd)
{
    const int tid = threadIdx.x;
    const int tx = tid & 15, ty = tid >> 4;
    __shared__ float As[8][128];
    __shared__ float Bs[8][128];
    const int arow = tid >> 1, acol = (tid & 1) * 4;
    const int brow = tid >> 5, bcol = (tid & 31) * 4;

    float acc[8][8];
#pragma unroll
    for (int i = 0; i < 8; i++)
#pragma unroll
        for (int j = 0; j < 8; j++) acc[i][j] = 0.f;

    for (int k0 = 0; k0 < Kd; k0 += 8) {
        float4 av = *(const float4*)(Athr + k0);
        float4 bv = *(const float4*)(Bthr + (size_t)k0 * ldb);
        if (k0) __syncthreads();
        As[acol + 0][arow] = av.x;
        As[acol + 1][arow] = av.y;
        As[acol + 2][arow] = av.z;
        As[acol + 3][arow] = av.w;
        *(float4*)&Bs[brow][bcol] = bv;
        __syncthreads();
#pragma unroll
        for (int kk = 0; kk < 8; ++kk) {
            float a[8], b[8];
            *(float4*)(a)     = *(const float4*)&As[kk][ty * 8];
            *(float4*)(a + 4) = *(const float4*)&As[kk][ty * 8 + 4];
            *(float4*)(b)     = *(const float4*)&Bs[kk][tx * 8];
            *(float4*)(b + 4) = *(const float4*)&Bs[kk][tx * 8 + 4];
#pragma unroll
            for (int i = 0; i < 8; i++)
#pragma unroll
                for (int j = 0; j < 8; j++) acc[i][j] += a[i] * b[j];
        }
    }
#pragma unroll
    for (int i = 0; i < 8; i++) {
        float* crow = Cblk + (size_t)(ty * 8 + i) * ldc + tx * 8;
#pragma unroll
        for (int j = 0; j < 8; j += 4) {
            float4 o = make_float4(acc[i][j], acc[i][j+1], acc[i][j+2], acc[i][j+3]);
            *(float4*)(crow + j) = o;
        }
    }
}

// ---------------------------------------------------------------------------
// Kernel 1: fused QKV projection.  C[8192,3072] = X[8192,1024] @ Wqkv
// Column j: region = j>>10 (0=q,1=k,2=v), head = (j>>6)&15, kcol = j&63.
// Region/head boundaries are 128-aligned, so per-thread pointer setup is
// loop-invariant.
// ---------------------------------------------------------------------------
__global__ void __launch_bounds__(256, 2) qkv_gemm_kernel(
    const float* __restrict__ x,  const float* __restrict__ wq,
    const float* __restrict__ wk, const float* __restrict__ wv)
{
    const int bm = blockIdx.y * 128, bn = blockIdx.x * 128;
    const int tid = threadIdx.x;
    const int arow = tid >> 1, acol = (tid & 1) * 4;
    const int brow = tid >> 5, bcol = (tid & 31) * 4;

    const int j = bn + bcol;
    const int which = j >> 10;
    const float* wsel = (which == 0) ? wq : (which == 1) ? wk : wv;
    const int h = (j >> 6) & (HEADS - 1);
    const int kc = j & (KDIM - 1);
    // element (d = brow, col kc) of head h: wsel[h*1024*64 + d*64 + kc]
    const float* Bthr = wsel + ((size_t)h * EMBED + brow) * KDIM + kc;
    const float* Athr = x + (size_t)(bm + arow) * EMBED + acol;
    sgemm_tile(Athr, Bthr, KDIM, g_qkv + (size_t)bm * QKVW + bn, QKVW, EMBED);
}

// ---------------------------------------------------------------------------
// Kernel 2: flash attention, fp32.  One block: 128 query rows for one (b,h).
// 256 threads, micro layout: rows ty*8+i (ty=tid/16), cols tx*4+j (tx=tid%16).
// ---------------------------------------------------------------------------
#define ATT_BM 128
#define ATT_BN 64
// shared layout (floats):
#define QS_PITCH 128
#define KS_PITCH 68
#define VS_PITCH 68
#define PS_PITCH 129
#define SM_QS    0
#define SM_KS    (SM_QS + 64 * QS_PITCH)              /* 8192  */
#define SM_VS    (SM_KS + 64 * KS_PITCH)              /* +4352 */
#define SM_PS    (SM_VS + 64 * VS_PITCH)              /* +4352 */
#define SM_FLOATS (SM_PS + 64 * PS_PITCH)             /* +8256 = 25152 */
#define ATT_SMEM_BYTES (SM_FLOATS * 4)                /* 100608 B */

extern __shared__ float att_smem[];

__global__ void __launch_bounds__(256, 2) attn_kernel()
{
    float* Qs = att_smem + SM_QS;  // [d][row]
    float* Ks = att_smem + SM_KS;  // [d][key]
    float* Vs = att_smem + SM_VS;  // [key][d]
    float* Ps = att_smem + SM_PS;  // [key][row]

    const int tid = threadIdx.x;
    const int tx = tid & 15, ty = tid >> 4;
    const int bh = blockIdx.y;
    const int b = bh >> 4, h = bh & (HEADS - 1);
    const int q0 = blockIdx.x * ATT_BM;

    const float* qbase = g_qkv + (size_t)b * SEQ * QKVW + h * KDIM;
    const float* kbase = qbase + EMBED;
    const float* vbase = qbase + 2 * EMBED;

    // Load Q tile transposed into Qs[d][r]
    {
        const int r = tid >> 1, d0 = (tid & 1) * 32;
        const float* src = qbase + (size_t)(q0 + r) * QKVW + d0;
#pragma unroll
        for (int u = 0; u < 32; u += 4) {
            float4 v = *(const float4*)(src + u);
            Qs[(d0 + u + 0) * QS_PITCH + r] = v.x;
            Qs[(d0 + u + 1) * QS_PITCH + r] = v.y;
            Qs[(d0 + u + 2) * QS_PITCH + r] = v.z;
            Qs[(d0 + u + 3) * QS_PITCH + r] = v.w;
        }
    }

    float m_i[8], l_i[8], acc[8][4];
#pragma unroll
    for (int i = 0; i < 8; i++) {
        m_i[i] = -1e30f; l_i[i] = 0.f;
#pragma unroll
        for (int j = 0; j < 4; j++) acc[i][j] = 0.f;
    }
    const float scale = 0.125f;  // 1/sqrt(64)

    for (int kt = 0; kt < SEQ; kt += ATT_BN) {
        __syncthreads();   // prior-iter reads of Ks/Vs/Ps done; Qs store ordered (1st iter)
        // Load K (transposed) and V (natural) tiles
        {
            const int c = tid >> 2, d0 = (tid & 3) * 16;
            const float* ksrc = kbase + (size_t)(kt + c) * QKVW + d0;
            const float* vsrc = vbase + (size_t)(kt + c) * QKVW + d0;
#pragma unroll
            for (int u = 0; u < 16; u += 4) {
                float4 k4 = *(const float4*)(ksrc + u);
                Ks[(d0 + u + 0) * KS_PITCH + c] = k4.x;
                Ks[(d0 + u + 1) * KS_PITCH + c] = k4.y;
                Ks[(d0 + u + 2) * KS_PITCH + c] = k4.z;
                Ks[(d0 + u + 3) * KS_PITCH + c] = k4.w;
                *(float4*)&Vs[c * VS_PITCH + d0 + u] = *(const float4*)(vsrc + u);
            }
        }
        __syncthreads();

        // S tile: s[i][j] = sum_d Q[r][d] * K[c][d]
        float s[8][4];
#pragma unroll
        for (int i = 0; i < 8; i++)
#pragma unroll
            for (int j = 0; j < 4; j++) s[i][j] = 0.f;
#pragma unroll 8
        for (int d = 0; d < 64; ++d) {
            float a[8], bb[4];
            *(float4*)(a)     = *(const float4*)&Qs[d * QS_PITCH + ty * 8];
            *(float4*)(a + 4) = *(const float4*)&Qs[d * QS_PITCH + ty * 8 + 4];
            *(float4*)(bb)    = *(const float4*)&Ks[d * KS_PITCH + tx * 4];
#pragma unroll
            for (int i = 0; i < 8; i++)
#pragma unroll
                for (int j = 0; j < 4; j++) s[i][j] += a[i] * bb[j];
        }

        // Online softmax (row stats shared by the 16 tx lanes via shfl, width 16)
#pragma unroll
        for (int i = 0; i < 8; i++) {
            float lm = -1e30f;
#pragma unroll
            for (int j = 0; j < 4; j++) { s[i][j] *= scale; lm = fmaxf(lm, s[i][j]); }
#pragma unroll
            for (int off = 8; off; off >>= 1)
                lm = fmaxf(lm, __shfl_xor_sync(0xffffffffu, lm, off, 16));
            const float mn = fmaxf(m_i[i], lm);
            const float f = __expf(m_i[i] - mn);
            m_i[i] = mn;
            float ls = 0.f;
#pragma unroll
            for (int j = 0; j < 4; j++) {
                float p = __expf(s[i][j] - mn);
                s[i][j] = p; ls += p;
            }
#pragma unroll
            for (int off = 8; off; off >>= 1)
                ls += __shfl_xor_sync(0xffffffffu, ls, off, 16);
            l_i[i] = l_i[i] * f + ls;
#pragma unroll
            for (int j = 0; j < 4; j++) acc[i][j] *= f;
#pragma unroll
            for (int j = 0; j < 4; j++)
                Ps[(tx * 4 + j) * PS_PITCH + ty * 8 + i] = s[i][j];
        }
        __syncthreads();

        // acc += P @ V
#pragma unroll 4
        for (int c = 0; c < ATT_BN; ++c) {
            float a[8];
#pragma unroll
            for (int i = 0; i < 8; i++) a[i] = Ps[c * PS_PITCH + ty * 8 + i];
            const float4 bv = *(const float4*)&Vs[c * VS_PITCH + tx * 4];
            const float bb[4] = {bv.x, bv.y, bv.z, bv.w};
#pragma unroll
            for (int i = 0; i < 8; i++)
#pragma unroll
                for (int j = 0; j < 4; j++) acc[i][j] += a[i] * bb[j];
        }
    }

    // Epilogue: heads[(b*SEQ + q0 + r)][h*64 + c] = acc / l
#pragma unroll
    for (int i = 0; i < 8; i++) {
        const float inv = 1.0f / l_i[i];
        float4 o = make_float4(acc[i][0]*inv, acc[i][1]*inv, acc[i][2]*inv, acc[i][3]*inv);
        *(float4*)&g_heads[(size_t)(b * SEQ + q0 + ty * 8 + i) * EMBED + h * KDIM + tx * 4] = o;
    }
}

// ---------------------------------------------------------------------------
// Kernel 3: output projection.  out[8192,1024] = heads[8192,1024] @ w[1024,1024]
// ---------------------------------------------------------------------------
__global__ void __launch_bounds__(256, 2) out_gemm_kernel(
    const float* __restrict__ w, float* __restrict__ out)
{
    const int bm = blockIdx.y * 128, bn = blockIdx.x * 128;
    const int tid = threadIdx.x;
    const int arow = tid >> 1, acol = (tid & 1) * 4;
    const int brow = tid >> 5, bcol = (tid & 31) * 4;
    const float* Athr = g_heads + (size_t)(bm + arow) * EMBED + acol;
    const float* Bthr = w + (size_t)brow * EMBED + bn + bcol;
    sgemm_tile(Athr, Bthr, EMBED, out + (size_t)bm * EMBED + bn, EMBED, EMBED);
}

// ---------------------------------------------------------------------------
extern "C" void kernel_launch(void* const* d_in, const int* in_sizes, int n_in,
                              void* d_out, int out_size)
{
    const float* x  = (const float*)d_in[0];
    const float* wq = (const float*)d_in[1];
    const float* wk = (const float*)d_in[2];
    const float* wv = (const float*)d_in[3];
    const float* w  = (const float*)d_in[4];
    float* out = (float*)d_out;

    // Idempotent, not a stream op — safe under graph capture.
    cudaFuncSetAttribute(attn_kernel,
                         cudaFuncAttributeMaxDynamicSharedMemorySize,
                         ATT_SMEM_BYTES);

    dim3 g1(QKVW / 128, TOKENS / 128);    // 24 x 64
    qkv_gemm_kernel<<<g1, 256>>>(x, wq, wk, wv);

    dim3 g2(SEQ / ATT_BM, BATCH * HEADS); // 16 x 64
    attn_kernel<<<g2, 256, ATT_SMEM_BYTES>>>();

    dim3 g3(EMBED / 128, TOKENS / 128);   // 8 x 64
    out_gemm_kernel<<<g3, 256>>>(w, out);
}